// round 1
// baseline (speedup 1.0000x reference)
#include <cuda_runtime.h>
#include <math.h>

// Problem shape (fixed by the dataset): A=128 atoms, FR=16 partials,
// NS=32768 samples, NF=128 frames. A is derived from in_sizes at launch.
#define FR 16
#define NS 32768
#define NF 128
#define A_MAX 128

#define TPB 256   // threads per block (main kernel)
#define KPT 8     // samples per thread -> tile of 2048 samples per block

// Scratch (no allocations allowed): per-(atom,partial) params + decay table.
__device__ double g_f2p[A_MAX * FR];              // freq / (2*pi), exact fp64 of the fp32 freq
__device__ float  g_amp2[A_MAX * FR];             // amp^2 (fp32, matching reference rounding)
__device__ float  g_dec[A_MAX * FR * (NF + 1)];   // d^(j+1), j=0..127, +1 duplicated tail for clamped lerp

// ---------------------------------------------------------------------------
// Setup: compute per-(a,f) frequency (as turns/sample), amp^2, and the
// 128-entry geometric decay table. 2048 independent threads; trivial cost.
// ---------------------------------------------------------------------------
__global__ void setup_kernel(const float* __restrict__ osc,
                             const float* __restrict__ amp,
                             const float* __restrict__ decay,
                             int n)
{
    int i = blockIdx.x * blockDim.x + threadIdx.x;
    if (i >= n) return;

    // freq = fl32( fl32(sigmoid(osc)^2) * fl32(pi) )  -- replicate fp32 rounding chain
    float o  = osc[i];
    float sg = (float)(1.0 / (1.0 + exp(-(double)o)));   // correctly-rounded sigmoid
    float fq = sg * sg;
    fq = fq * 3.14159265358979323846f;                    // literal rounds to fl32(pi)
    g_f2p[i] = (double)fq * (1.0 / (2.0 * M_PI));         // turns per sample (fp64)

    float am = amp[i];
    g_amp2[i] = am * am;

    // d = 0.7 + sigmoid(decay)*0.299999 ; dec[j] = d^(j+1)
    float dv  = decay[i];
    float sgd = (float)(1.0 / (1.0 + exp(-(double)dv)));
    float d   = 0.7f + sgd * 0.299999f;

    float cur = 1.0f;
    float* row = &g_dec[(size_t)i * (NF + 1)];
    for (int j = 0; j < NF; j++) {
        cur *= d;               // geometric chain; matches exp(cumsum(log(d))) to ~1e-5 rel
        row[j] = cur;
    }
    row[NF] = cur;              // duplicate last entry: lerp with i1 clamped to 127
}

// ---------------------------------------------------------------------------
// Main synth: block = (atom, 2048-sample tile). Each thread produces KPT=8
// strided samples (coalesced stores). Phase reduced mod 1 turn in fp64
// (exact vs. the closed form), sin via __sinf on the reduced argument.
// ---------------------------------------------------------------------------
__global__ void __launch_bounds__(TPB)
synth_kernel(float* __restrict__ out)
{
    __shared__ float  s_dec[FR][NF + 2];  // +pad
    __shared__ double s_f2p[FR];
    __shared__ float  s_a2[FR];

    const int a    = blockIdx.y;
    const int base = blockIdx.x * (TPB * KPT);
    const int tid  = threadIdx.x;
    const int ab   = a * FR;

    if (tid < FR) {
        s_f2p[tid] = g_f2p[ab + tid];
        s_a2[tid]  = g_amp2[ab + tid];
    }
    for (int idx = tid; idx < FR * (NF + 1); idx += TPB) {
        int f = idx / (NF + 1);
        int j = idx % (NF + 1);
        s_dec[f][j] = g_dec[(size_t)(ab + f) * (NF + 1) + j];
    }
    __syncthreads();

    // Precompute per-sample quantities shared across all 16 partials.
    double td[KPT];
    float  w8[KPT];
    int    i08[KPT];
#pragma unroll
    for (int k = 0; k < KPT; k++) {
        int t = base + k * TPB + tid;
        td[k] = (double)(t + 1);
        // pos = (t+0.5)/256 - 0.5, exact in fp32 for all t < 2^15; clip low to 0.
        float pos = fmaf((float)t, 0.00390625f, -0.498046875f);
        pos = fmaxf(pos, 0.0f);
        float fi = floorf(pos);
        i08[k] = (int)fi;       // 0..127
        w8[k]  = pos - fi;      // exact lerp weight
    }

    float acc[KPT];
#pragma unroll
    for (int k = 0; k < KPT; k++) acc[k] = 0.0f;

#pragma unroll 1
    for (int f = 0; f < FR; f++) {
        const double f2p  = s_f2p[f];
        const float  a2   = s_a2[f];
        const float* drow = s_dec[f];
#pragma unroll
        for (int k = 0; k < KPT; k++) {
            double turns = td[k] * f2p;                 // exact closed-form phase / 2pi
            double fr    = turns - rint(turns);         // [-0.5, 0.5], fp64-exact reduction
            float  x     = (float)fr * 6.28318530717958647692f;  // fl32(2pi)
            float  sv    = __sinf(x);                   // |x| <= pi: MUFU fast path, ~2^-21 abs err
            float  d0    = drow[i08[k]];                // warp-broadcast (i0 constant per 256-sample frame)
            float  d1    = drow[i08[k] + 1];
            float  D     = fmaf(w8[k], d1 - d0, d0);
            acc[k] = fmaf(sv * a2, D, acc[k]);
        }
    }

    float* o = out + (size_t)a * NS + base + tid;
#pragma unroll
    for (int k = 0; k < KPT; k++)
        o[k * TPB] = acc[k] * 0.0625f;                  // mean over 16 partials
}

// ---------------------------------------------------------------------------
extern "C" void kernel_launch(void* const* d_in, const int* in_sizes, int n_in,
                              void* d_out, int out_size)
{
    const float* osc   = (const float*)d_in[0];
    const float* amp   = (const float*)d_in[1];
    const float* decay = (const float*)d_in[2];
    // d_in[3] = n_samples (32768), d_in[4] = n_frames (128): fixed-shape problem.

    int n = in_sizes[0];      // A * FR
    int A = n / FR;

    setup_kernel<<<(n + 255) / 256, 256>>>(osc, amp, decay, n);

    dim3 grid(NS / (TPB * KPT), A);   // (16, 128)
    synth_kernel<<<grid, TPB>>>((float*)d_out);
}

// round 2
// speedup vs baseline: 1.7435x; 1.7435x over previous
#include <cuda_runtime.h>
#include <math.h>

// Fixed problem shape: A=128 atoms, FR=16 partials, NS=32768 samples, NF=128 frames.
#define FR 16
#define NS 32768
#define NF 128
#define A_MAX 128

#define TPB 256
#define KPT 8          // samples per thread -> 2048-sample tile per block
#define JW  10         // decay-frame window entries a 2048-sample tile can touch

// Scratch (no allocations allowed).
__device__ unsigned g_phi[A_MAX * FR];          // round(freq/2pi * 2^32): fixed-point turns/sample
__device__ float    g_a2n[A_MAX * FR];          // -amp^2/16 (sign folds the half-turn shift, /16 the mean)
__device__ float2   g_pair[A_MAX * FR * NF];    // {dec[j], dec[j+1]-dec[j]}, slope clamped to 0 at j=127

// ---------------------------------------------------------------------------
// Setup: per-(atom,partial) fixed-point frequency, scaled amplitude, and the
// 128-entry (value, slope) decay table. 2048 threads; trivial cost.
// ---------------------------------------------------------------------------
__global__ void setup_kernel(const float* __restrict__ osc,
                             const float* __restrict__ amp,
                             const float* __restrict__ decay,
                             int n)
{
    int i = blockIdx.x * blockDim.x + threadIdx.x;
    if (i >= n) return;

    // freq = fl32( fl32(sigmoid(osc)^2) * fl32(pi) ) -- replicate fp32 rounding chain
    float o  = osc[i];
    float sg = (float)(1.0 / (1.0 + exp(-(double)o)));   // correctly-rounded sigmoid
    float fq = sg * sg;
    fq = fq * 3.14159265358979323846f;
    double f2p = (double)fq * (1.0 / (2.0 * M_PI));       // turns/sample, < 0.5
    g_phi[i] = (unsigned)llrint(f2p * 4294967296.0);      // Q0.32 turns

    float am = amp[i];
    g_a2n[i] = -(am * am) * 0.0625f;                      // -amp^2 / 16

    // d = 0.7 + sigmoid(decay)*0.299999 ; dec[j] = d^(j+1), j=0..127
    float dv  = decay[i];
    float sgd = (float)(1.0 / (1.0 + exp(-(double)dv)));
    float d   = 0.7f + sgd * 0.299999f;

    float2* row = &g_pair[(size_t)i * NF];
    float cur = d;
    for (int j = 0; j < NF; j++) {
        float nxt = cur * d;
        row[j] = make_float2(cur, (j == NF - 1) ? 0.0f : (nxt - cur)); // i1 clamp -> slope 0
        cur = nxt;
    }
}

// ---------------------------------------------------------------------------
// Synth: block = (atom, 2048-sample tile). Phase via 32-bit fixed-point
// multiply (wraps mod 1 turn), bit-cast to [1,2) float, one FFMA to radians,
// MUFU sin. Decay lerp from a 10-entry-per-partial smem window via LDS.64.
// ---------------------------------------------------------------------------
__global__ void __launch_bounds__(TPB)
synth_kernel(float* __restrict__ out)
{
    __shared__ float2   s_pair[FR][JW];
    __shared__ unsigned s_phi[FR];
    __shared__ float    s_a2[FR];

    const int a    = blockIdx.y;
    const int base = blockIdx.x * (TPB * KPT);
    const int tid  = threadIdx.x;
    const int ab   = a * FR;

    int jb = (base >> 8) - 1;            // first frame index this tile can touch
    if (jb < 0) jb = 0;

    if (tid < FR) {
        s_phi[tid] = g_phi[ab + tid];
        s_a2[tid]  = g_a2n[ab + tid];
    }
    for (int idx = tid; idx < FR * JW; idx += TPB) {
        int f = idx / JW, jl = idx % JW;
        int j = jb + jl; if (j > NF - 1) j = NF - 1;
        s_pair[f][jl] = g_pair[(size_t)(ab + f) * NF + j];
    }
    __syncthreads();

    // Per-sample quantities shared across all 16 partials.
    unsigned tk1[KPT];
    float    w[KPT];
    int      offb[KPT];
#pragma unroll
    for (int k = 0; k < KPT; k++) {
        int t = base + k * TPB + tid;
        tk1[k] = (unsigned)(t + 1);
        // pos = (t+0.5)/256 - 0.5, exact in fp32 for all t < 2^15; clip low to 0.
        float pos = fmaf((float)t, 0.00390625f, -0.498046875f);
        pos = fmaxf(pos, 0.0f);
        float fi = floorf(pos);
        w[k]    = pos - fi;
        offb[k] = ((int)fi - jb) * 8;     // byte offset into the smem window
    }

    float acc[KPT];
#pragma unroll
    for (int k = 0; k < KPT; k++) acc[k] = 0.0f;

    const char* pairbase = (const char*)&s_pair[0][0];

#pragma unroll
    for (int f = 0; f < FR; f++) {
        const unsigned phi = s_phi[f];
        const float    a2  = s_a2[f];
        const char*    prw = pairbase + f * (JW * 8);
#pragma unroll
        for (int k = 0; k < KPT; k++) {
            unsigned p = tk1[k] * phi;                     // (t+1)*phi mod 2^32 == phase mod 1 turn
            float v  = __uint_as_float((p >> 9) | 0x3F800000u);  // 1 + frac, in [1,2)
            float x  = fmaf(v, 6.28318530717958647692f,
                              -9.42477796076937971538f);   // 2*pi*frac - pi, in [-pi,pi)
            float sv = __sinf(x);                          // = -sin(2*pi*frac)
            float2 ds = *(const float2*)(prw + offb[k]);   // {value, slope}, LDS.64
            float D  = fmaf(w[k], ds.y, ds.x);
            acc[k] = fmaf(sv * a2, D, acc[k]);             // a2 carries -amp^2/16
        }
    }

    float* o = out + (size_t)a * NS + base + tid;
#pragma unroll
    for (int k = 0; k < KPT; k++)
        o[k * TPB] = acc[k];
}

// ---------------------------------------------------------------------------
extern "C" void kernel_launch(void* const* d_in, const int* in_sizes, int n_in,
                              void* d_out, int out_size)
{
    const float* osc   = (const float*)d_in[0];
    const float* amp   = (const float*)d_in[1];
    const float* decay = (const float*)d_in[2];

    int n = in_sizes[0];      // A * FR
    int A = n / FR;

    setup_kernel<<<(n + 255) / 256, 256>>>(osc, amp, decay, n);

    dim3 grid(NS / (TPB * KPT), A);   // (16, 128)
    synth_kernel<<<grid, TPB>>>((float*)d_out);
}

// round 3
// speedup vs baseline: 3.1538x; 1.8089x over previous
#include <cuda_runtime.h>
#include <math.h>

// Fixed problem shape: A=128 atoms, FR=16 partials, NS=32768 samples, NF=128 frames.
#define FR  16
#define NS  32768
#define NF  128
#define TPB 256
#define KPT 8                       // samples/thread -> 2048-sample tile; 1 frame per k step
#define NBX (NS / (TPB * KPT))      // 16 x-blocks

// 2*pi / 2^32 : converts signed Q0.32 turns to radians in [-pi, pi)
#define TURN2RAD 1.4629180792671596e-9f

// ---------------------------------------------------------------------------
// Single fused kernel. Block = (atom, 2048-sample tile).
// Threads 0..15 derive the 16 partials' parameters from the raw inputs
// (freq as Q0.32 fixed-point turns/sample; amp^2/16; decay base d and the
// two per-half-warp decay anchors a2*d^J, a2*d^(J+1)). The decay lerp
// factorizes exactly over the geometric table, so the mainloop is pure
// register math: fixed-point phase add, I2F, one FMUL to radians, MUFU sin,
// FFMA accumulate, FMUL decay update. No per-item memory traffic.
// ---------------------------------------------------------------------------
__global__ void __launch_bounds__(TPB)
synth_kernel(const float* __restrict__ osc,
             const float* __restrict__ amp,
             const float* __restrict__ decay,
             float* __restrict__ out)
{
    __shared__ float4 s_cst[FR];    // {phi bits, d, a2*d^J, a2*d^(J+1)}

    const int a    = blockIdx.y;
    const int bx   = blockIdx.x;
    const int base = bx * (TPB * KPT);
    const int tid  = threadIdx.x;
    const int J    = bx * KPT;      // first (unclamped) frame this tile's h=1 half touches

    if (tid < FR) {
        int i = a * FR + tid;
        // freq = fl32( fl32(sigmoid(osc)^2) * fl32(pi) )  (replicate fp32 rounding chain)
        float o   = osc[i];
        float sgf = (float)(1.0 / (1.0 + exp(-(double)o)));    // correctly-rounded sigmoid
        float t1  = sgf * sgf;
        float fq  = t1 * 3.14159274101257324219f;              // fl32(pi)
        double f2p = (double)fq * (1.0 / (2.0 * M_PI));        // turns/sample, < 0.5
        unsigned phi = (unsigned)llrint(f2p * 4294967296.0);   // Q0.32 turns

        float am = amp[i];
        float a2 = am * am * 0.0625f;                          // amp^2 / 16 (mean over partials)

        // d = 0.7 + sigmoid(decay)*0.299999
        float dv  = decay[i];
        float sgd = (float)(1.0 / (1.0 + exp(-(double)dv)));
        float d   = 0.7f + sgd * 0.299999f;

        float l2d = (float)log2((double)d);
        float Eh0 = a2 * exp2f((float)J * l2d);                // a2 * d^J
        float Eh1 = Eh0 * d;                                   // a2 * d^(J+1)

        s_cst[tid] = make_float4(__uint_as_float(phi), d, Eh0, Eh1);
    }
    __syncthreads();

    // Per-thread constants (identical across all 16 partials):
    const int  h  = tid >> 7;                                  // which half of the 256-thread tile
    // lerp weight w = frac((t+0.5)/256 - 0.5); constant across k for this thread
    const float w = fmaf((float)tid, 0.00390625f,
                         h ? -0.498046875f : 0.501953125f);
    const unsigned tk10 = (unsigned)(base + tid + 1);          // (t+1) at k=0
    const bool fix_first = (bx == 0)       && (h == 0);        // pos clamped to 0 at k=0
    const bool fix_last  = (bx == NBX - 1) && (h == 1);        // i1 clamped at 127 at k=7

    float acc[KPT];
#pragma unroll
    for (int k = 0; k < KPT; k++) acc[k] = 0.0f;

#pragma unroll 2
    for (int f = 0; f < FR; f++) {
        const float4  cst = s_cst[f];
        const unsigned phi = __float_as_uint(cst.x);
        const float    d   = cst.y;
        const float    Eh  = h ? cst.w : cst.z;                // a2 * d^(J+h)
        const float    wf  = fmaf(w, d - 1.0f, 1.0f);          // (1-w) + w*d
        float    E  = Eh * wf;                                 // a2 * d^(j0+1) * lerp factor
        unsigned p  = tk10 * phi;                              // phase in turns, mod 1 (Q0.32)
        const unsigned dp = phi << 8;                          // 256 samples per k step

        // k = 0 (fix: first 128 samples have pos clamped to 0 -> D = d exactly)
        {
            float sv = __sinf((float)(int)p * TURN2RAD);
            float Eu = fix_first ? cst.w : E;                  // cst.w = a2*d when bx==0
            acc[0] = fmaf(sv, Eu, acc[0]);
            p += dp;  E *= d;
        }
#pragma unroll
        for (int k = 1; k < KPT - 1; k++) {
            float sv = __sinf((float)(int)p * TURN2RAD);
            acc[k] = fmaf(sv, E, acc[k]);
            p += dp;  E *= d;
        }
        // k = 7 (fix: last 128 samples have i1 clamped -> D = d^128, no lerp factor)
        {
            float sv = __sinf((float)(int)p * TURN2RAD);
            float Eu = E;
            if (fix_last) Eu = E * __frcp_rn(wf);              // strip the lerp factor
            acc[KPT - 1] = fmaf(sv, Eu, acc[KPT - 1]);
        }
    }

    float* o = out + (size_t)a * NS + base + tid;
#pragma unroll
    for (int k = 0; k < KPT; k++)
        o[k * TPB] = acc[k];
}

// ---------------------------------------------------------------------------
extern "C" void kernel_launch(void* const* d_in, const int* in_sizes, int n_in,
                              void* d_out, int out_size)
{
    const float* osc   = (const float*)d_in[0];
    const float* amp   = (const float*)d_in[1];
    const float* decay = (const float*)d_in[2];

    int A = in_sizes[0] / FR;

    dim3 grid(NBX, A);                      // (16, 128)
    synth_kernel<<<grid, TPB>>>(osc, amp, decay, (float*)d_out);
}

// round 4
// speedup vs baseline: 5.0656x; 1.6062x over previous
#include <cuda_runtime.h>
#include <math.h>

// Fixed problem shape: A=128 atoms, FR=16 partials, NS=32768 samples, NF=128 frames.
#define FR  16
#define NS  32768
#define NF  128
#define TPB 256
#define KPT 16                      // samples/thread; frame index advances 1 per k
#define NBX (NS / (TPB * KPT))      // 8 x-blocks

// 2*pi / 2^32 : signed Q0.32 turns -> radians in [-pi, pi)
#define TURN2RAD 1.4629180792671596e-9f

// ---------------------------------------------------------------------------
// Block = (atom, 4096-sample tile). Threads 0..15 derive per-partial constants:
//   c1 = { phi (Q0.32 turns/sample), dp = phi<<8, rc = 2*d*cos(delta), nc2 = -d^2 }
//   c2 = { Eh0 = a2*d^J, Eh1 = a2*d^(J+1), a2d = a2*d, dm1 = d-1 }
// Mainloop per (partial, thread): seed a damped-sinusoid Goertzel chain with
// two MUFU.SIN, then 14 steps of  y[k+1] = rc*y[k] + nc2*y[k-1]  (2 fma ops)
// + 1 accumulate each. The geometric-decay lerp factorizes into the chain
// scale exactly, so there is no per-sample memory traffic at all.
// ---------------------------------------------------------------------------
__global__ void __launch_bounds__(TPB)
synth_kernel(const float* __restrict__ osc,
             const float* __restrict__ amp,
             const float* __restrict__ decay,
             float* __restrict__ out)
{
    __shared__ float4 s_c1[FR];
    __shared__ float4 s_c2[FR];

    const int a    = blockIdx.y;
    const int bx   = blockIdx.x;
    const int base = bx * (TPB * KPT);
    const int tid  = threadIdx.x;
    const int J    = bx * KPT;

    if (tid < FR) {
        int i = a * FR + tid;
        // freq = fl32( fl32(sigmoid(osc)^2) * fl32(pi) )  (replicate fp32 rounding chain)
        float o   = osc[i];
        float sgf = (float)(1.0 / (1.0 + exp(-(double)o)));
        float t1  = sgf * sgf;
        float fq  = t1 * 3.14159274101257324219f;              // fl32(pi)
        double f2p = (double)fq * (1.0 / (2.0 * M_PI));        // turns/sample
        unsigned phi = (unsigned)llrint(f2p * 4294967296.0);   // Q0.32
        unsigned dp  = phi << 8;                               // 256 samples per k

        float am = amp[i];
        float a2 = am * am * 0.0625f;                          // amp^2 / 16

        float dv  = decay[i];
        float sgd = (float)(1.0 / (1.0 + exp(-(double)dv)));
        float d   = 0.7f + sgd * 0.299999f;

        // Goertzel constants for step angle delta = 2*pi*dp/2^32
        float del = (float)(int)dp * TURN2RAD;                 // [-pi, pi)
        float cd  = __cosf(del);
        float rc  = 2.0f * d * cd;
        float nc2 = -(d * d);

        float l2d = (float)log2((double)d);
        float Eh0 = a2 * exp2f((float)J * l2d);                // a2 * d^J
        float Eh1 = Eh0 * d;

        s_c1[tid] = make_float4(__uint_as_float(phi), __uint_as_float(dp), rc, nc2);
        s_c2[tid] = make_float4(Eh0, Eh1, a2 * d, d - 1.0f);
    }
    __syncthreads();

    const int  h  = tid >> 7;                                  // tile half
    // lerp weight w: constant across k for this thread
    const float w = fmaf((float)tid, 0.00390625f,
                         h ? -0.498046875f : 0.501953125f);
    const unsigned tk1 = (unsigned)(base + tid + 1);
    const bool fix_first = (bx == 0)       && (h == 0);        // pos clamp at k=0
    const bool fix_last  = (bx == NBX - 1) && (h == 1);        // i1 clamp at k=KPT-1

    float acc[KPT];
#pragma unroll
    for (int k = 0; k < KPT; k++) acc[k] = 0.0f;

#pragma unroll 4
    for (int f = 0; f < FR; f++) {
        const float4 c1 = s_c1[f];
        const float4 c2 = s_c2[f];
        const unsigned phi = __float_as_uint(c1.x);
        const unsigned dp  = __float_as_uint(c1.y);
        const float rc  = c1.z, nc2 = c1.w;
        const float Eh  = h ? c2.y : c2.x;                     // a2 * d^(J+h)
        const float dm1 = c2.w;
        const float wf  = fmaf(w, dm1, 1.0f);                  // (1-w) + w*d
        const float Ew  = Eh * wf;                             // chain scale at k=0

        unsigned p0 = tk1 * phi;                               // phase mod 1 turn
        unsigned p1 = p0 + dp;
        float s0 = __sinf((float)(int)p0 * TURN2RAD);
        float s1 = __sinf((float)(int)p1 * TURN2RAD);

        float ykm2 = s0 * Ew;                                  // y[0]
        float ykm1 = s1 * fmaf(Ew, dm1, Ew);                   // y[1] = s1 * Ew * d

        acc[0] = fmaf(s0, fix_first ? c2.z : Ew, acc[0]);      // c2.z = a2*d (exact clamp value)
        acc[1] += ykm1;

#pragma unroll
        for (int k = 2; k < KPT; k++) {
            float y = fmaf(rc, ykm1, nc2 * ykm2);              // damped-sinusoid recurrence
            if (k == KPT - 1 && fix_last)
                acc[k] += __fdividef(y, wf);                   // strip lerp factor: D = d^128 exact
            else
                acc[k] += y;
            ykm2 = ykm1;  ykm1 = y;
        }
    }

    float* o = out + (size_t)a * NS + base + tid;
#pragma unroll
    for (int k = 0; k < KPT; k++)
        o[k * TPB] = acc[k];
}

// ---------------------------------------------------------------------------
extern "C" void kernel_launch(void* const* d_in, const int* in_sizes, int n_in,
                              void* d_out, int out_size)
{
    const float* osc   = (const float*)d_in[0];
    const float* amp   = (const float*)d_in[1];
    const float* decay = (const float*)d_in[2];

    int A = in_sizes[0] / FR;

    dim3 grid(NBX, A);                      // (8, 128)
    synth_kernel<<<grid, TPB>>>(osc, amp, decay, (float*)d_out);
}